// round 15
// baseline (speedup 1.0000x reference)
#include <cuda_runtime.h>
#include <cuda_bf16.h>
#include <math.h>

#define HF 128
#define WF 128
#define DF 512
#define NA 65536
#define MAXDET 512
#define HIDDEN 1024
#define PDIM (9*512)   // 4608
#define NBIN 16384
#define NCAND 1024
#define SPLITK 2

typedef unsigned long long u64;
typedef unsigned int u32;

// hist layout: [0..NBIN) bins, control words, then per-tile tickets
#define H_THR   (NBIN + 0)
#define H_TOT   (NBIN + 1)
#define H_CNT   (NBIN + 2)
#define H_DONE  (NBIN + 3)
#define H_DONE2 (NBIN + 4)
#define T1OFF   (NBIN + 16)    // 128 tickets gemm1
#define T2OFF   (NBIN + 144)   // 128 tickets gemm2
#define CTRLN   (NBIN + 512)

// ---------------- device scratch (static, zero-initialized; self-cleaning) ----------------
__device__ __align__(16) u64   g_keys[NA];
__device__ __align__(16) u32   g_hist[CTRLN];
__device__ __align__(16) u64   g_cand[NCAND];
__device__ __align__(16) float g_sel[MAXDET*4];
__device__ float g_scores[MAXDET];
__device__ int   g_valid[MAXDET];
__device__ int   g_keep[MAXDET];
__device__ __align__(16) u32   g_mask[MAXDET*16];
__device__ __align__(16) float g_part[SPLITK * MAXDET * HIDDEN];

// bf16 hi/lo split activations & weights
__device__ __align__(16) __nv_bfloat16 g_Ahi[MAXDET*PDIM];
__device__ __align__(16) __nv_bfloat16 g_Alo[MAXDET*PDIM];
__device__ __align__(16) __nv_bfloat16 g_W1Th[HIDDEN*PDIM];
__device__ __align__(16) __nv_bfloat16 g_W1Tl[HIDDEN*PDIM];
__device__ __align__(16) __nv_bfloat16 g_W2Th[HIDDEN*HIDDEN];
__device__ __align__(16) __nv_bfloat16 g_W2Tl[HIDDEN*HIDDEN];
__device__ __align__(16) __nv_bfloat16 g_h1hi[MAXDET*HIDDEN];
__device__ __align__(16) __nv_bfloat16 g_h1lo[MAXDET*HIDDEN];
__device__ __align__(16) __nv_bfloat16 g_h2hi[MAXDET*HIDDEN];
__device__ __align__(16) __nv_bfloat16 g_h2lo[MAXDET*HIDDEN];

// ---------------- low-level helpers (plain sm_103-legal PTX only) ----------------
__device__ __forceinline__ u32 smem_u32(const void* p) {
    u32 a;
    asm("{ .reg .u64 t; cvta.to.shared.u64 t, %1; cvt.u32.u64 %0, t; }" : "=r"(a) : "l"(p));
    return a;
}
#define CPA16(dst, src) \
    asm volatile("cp.async.cg.shared.global [%0], [%1], 16;" :: "r"(dst), "l"(src) : "memory")
#define CPA_COMMIT() asm volatile("cp.async.commit_group;" ::: "memory")
#define CPA_WAIT0()  asm volatile("cp.async.wait_group 0;" ::: "memory")

__device__ __forceinline__ void ldsm4(u32* r, u32 addr) {
    asm volatile("ldmatrix.sync.aligned.m8n8.x4.shared.b16 {%0,%1,%2,%3}, [%4];"
                 : "=r"(r[0]), "=r"(r[1]), "=r"(r[2]), "=r"(r[3]) : "r"(addr));
}
__device__ __forceinline__ void ldsm2(u32* r, u32 addr) {
    asm volatile("ldmatrix.sync.aligned.m8n8.x2.shared.b16 {%0,%1}, [%2];"
                 : "=r"(r[0]), "=r"(r[1]) : "r"(addr));
}
__device__ __forceinline__ void mma16816(float* d, const u32* a, const u32* b) {
    asm volatile("mma.sync.aligned.m16n8k16.row.col.f32.bf16.bf16.f32 "
                 "{%0,%1,%2,%3}, {%4,%5,%6,%7}, {%8,%9}, {%0,%1,%2,%3};"
                 : "+f"(d[0]), "+f"(d[1]), "+f"(d[2]), "+f"(d[3])
                 : "r"(a[0]), "r"(a[1]), "r"(a[2]), "r"(a[3]), "r"(b[0]), "r"(b[1]));
}

// ---------------- 1) scores + keys + histogram + fused last-block scan ----------------
__global__ void score_kernel(const float* __restrict__ obj, u64* __restrict__ keys,
                             u32* __restrict__ hist) {
    int tid = threadIdx.x;
    int n = blockIdx.x * 256 + tid;
    {
        int cell = n >> 2;
        int k = n & 3;
        float o0 = obj[cell*8 + 2*k];
        float o1 = obj[cell*8 + 2*k + 1];
        float m  = fmaxf(o0, o1);
        float e0 = expf(o0 - m);
        float e1 = expf(o1 - m);
        float s  = e1 / (e0 + e1);
        u32 bits = (s > 0.5f) ? __float_as_uint(s) : __float_as_uint(-INFINITY);
        u32 mono = (bits & 0x80000000u) ? ~bits : (bits | 0x80000000u);
        keys[n] = ((u64)mono << 32) | (u32)(~n);
        if (mono > 0xBF000000u)
            atomicAdd(&hist[(mono - 0xBF000000u) >> 9], 1u);
    }
    __threadfence();
    __syncthreads();
    __shared__ int lastBlk;
    if (tid == 0) lastBlk = (atomicAdd(&hist[H_DONE], 1u) == (u32)(gridDim.x - 1)) ? 1 : 0;
    __syncthreads();
    if (!lastBlk) return;

    u32 h[64];
    u32 seg = 0;
    uint4* hp = (uint4*)(hist + tid*64);
    #pragma unroll
    for (int v = 0; v < 16; v++) {
        uint4 x = __ldcg(&hp[v]);
        h[v*4+0] = x.x; h[v*4+1] = x.y; h[v*4+2] = x.z; h[v*4+3] = x.w;
        seg += x.x + x.y + x.z + x.w;
    }
    __shared__ u32 ps[256];
    __shared__ u32 sh_thr;
    ps[255 - tid] = seg;
    if (tid == 0) sh_thr = 0;
    __syncthreads();
    for (int off = 1; off < 256; off <<= 1) {
        u32 y = (tid >= off) ? ps[tid - off] : 0;
        __syncthreads();
        ps[tid] += y;
        __syncthreads();
    }
    u32 inc = ps[255 - tid];
    u32 exc = inc - seg;
    if (exc < 512 && inc >= 512) {
        u32 c = exc;
        #pragma unroll
        for (int k = 63; k >= 0; k--) {
            c += h[k];
            if (c >= 512) { sh_thr = (u32)(tid*64 + k); break; }
        }
    }
    uint4 z4 = make_uint4(0u, 0u, 0u, 0u);
    #pragma unroll
    for (int v = 0; v < 16; v++) hp[v] = z4;
    __syncthreads();
    if (tid == 0) {
        hist[H_THR]  = sh_thr;
        hist[H_TOT]  = ps[255];
        hist[H_DONE] = 0;
    }
}

// ---------------- 2) compact candidates ----------------
__global__ void compact_kernel(const u64* __restrict__ keys, u32* __restrict__ hist,
                               u64* __restrict__ cand) {
    int n = blockIdx.x * 256 + threadIdx.x;
    u64 key = keys[n];
    u32 hi = (u32)(key >> 32);
    bool admit;
    if (hi > 0xBF000000u) admit = ((hi - 0xBF000000u) >> 9) >= hist[H_THR];
    else                  admit = (hist[H_TOT] < 512);
    if (admit) {
        u32 p = atomicAdd(&hist[H_CNT], 1u);
        if (p < NCAND) cand[p] = key;
    }
}

// ---------------- 3) rank-sort candidates + direct scatter-decode ----------------
__global__ void __launch_bounds__(1024) select_sort_kernel(const u64* __restrict__ cand,
                                                           u32* __restrict__ hist,
                                                           const float* __restrict__ reg) {
    __shared__ u64 s[NCAND];
    int tid = threadIdx.x;
    u32 cn = hist[H_CNT];
    if (cn > NCAND) cn = NCAND;
    s[tid] = (tid < (int)cn) ? cand[tid] : 0ULL;
    __syncthreads();
    if (tid == 0) {                 // self-clean after last use
        hist[H_CNT] = 0;
        hist[H_THR] = 0;
        hist[H_TOT] = 0;
    }

    // O(C^2) rank sort; keys unique -> direct scatter of decoded outputs
    if (tid < (int)cn) {
        u64 my = s[tid];
        int cnr = ((int)cn + 1) & ~1;    // round to pairs (padding is 0)
        int rank = 0;
        for (int j = 0; j < cnr; j += 2) {
            u64 a = s[j], b = s[j+1];
            rank += (a > my) + (b > my);
        }
        if (rank < 512) {
            u32 lo = (u32)my;
            u32 hi = (u32)(my >> 32);
            u32 n  = ~lo;
            u32 fb = (hi & 0x80000000u) ? (hi ^ 0x80000000u) : ~hi;
            float sc = __uint_as_float(fb);
            int k = n & 3;
            int j = (n >> 2) & 127;
            int i = n >> 9;
            float sz = (float)((k + 1) * 32);
            int base = ((i*128 + j) * 16) + k*4;
            float r0 = reg[base+0], r1 = reg[base+1], r2 = reg[base+2], r3 = reg[base+3];
            float acx = j * 16.0f + 8.0f;
            float acy = i * 16.0f + 8.0f;
            float cx = acx + r0 * sz;
            float cy = acy + r1 * sz;
            float ww = sz * expf(r2);
            float hh = sz * expf(r3);
            int valid = (sc > 0.5f) ? 1 : 0;
            g_sel[rank*4+0] = cx - ww*0.5f;
            g_sel[rank*4+1] = cy - hh*0.5f;
            g_sel[rank*4+2] = ww;
            g_sel[rank*4+3] = hh;
            g_scores[rank] = valid ? sc : 0.0f;
            g_valid[rank]  = valid;
        }
    } else if (tid < 512) {          // unfilled tail slots when cn < 512
        g_sel[tid*4+0] = 0.0f;
        g_sel[tid*4+1] = 0.0f;
        g_sel[tid*4+2] = 0.0f;
        g_sel[tid*4+3] = 0.0f;
        g_scores[tid] = 0.0f;
        g_valid[tid]  = 0;
    }
}

// ---------------- 4) IoU ballot matrix + fused last-block NMS scan ----------------
__global__ void __launch_bounds__(512) iou_nms_kernel(u32* __restrict__ hist) {
    __shared__ float4 bx[512];
    int i = blockIdx.x;
    int j = threadIdx.x;
    bx[j] = ((const float4*)g_sel)[j];
    __syncthreads();
    {
        float4 a = bx[i], b = bx[j];
        float ax2 = a.x + a.z, ay2 = a.y + a.w;
        float bx2 = b.x + b.z, by2 = b.y + b.w;
        float ix = fmaxf(0.0f, fminf(ax2, bx2) - fmaxf(a.x, b.x));
        float iy = fmaxf(0.0f, fminf(ay2, by2) - fmaxf(a.y, b.y));
        float inter = ix * iy;
        float iou = inter / (a.z*a.w + b.z*b.w - inter + 1e-8f);
        u32 ball = __ballot_sync(0xffffffffu, iou > 0.3f);
        if ((j & 31) == 0) g_mask[i*16 + (j >> 5)] = ball;
    }
    __threadfence();
    __syncthreads();
    __shared__ int lastBlk;
    if (j == 0) lastBlk = (atomicAdd(&hist[H_DONE2], 1u) == (u32)(gridDim.x - 1)) ? 1 : 0;
    __syncthreads();
    if (!lastBlk) return;

    // last block: stage masks+valid, run warp-0 greedy scan
    __shared__ u32 msk[512][16];
    __shared__ int sval[512];
    int lane = j & 31, w = j >> 5;
    #pragma unroll
    for (int r = 0; r < 16; r++) {
        int row = (j >> 4) + r*32;
        msk[row][j & 15] = __ldcg(&g_mask[row*16 + (j & 15)]);
    }
    sval[j] = g_valid[j];
    __syncthreads();
    if (j == 0) hist[H_DONE2] = 0;   // self-clean
    if (w == 0) {
        u32 removed = 0;   // lane l (<16) owns word l of the suppression set
        for (int i2 = 0; i2 < 512; i2++) {
            int wi = i2 >> 5, bi = i2 & 31;
            u32 rword = __shfl_sync(0xffffffffu, removed, wi);
            int k = sval[i2] && !((rword >> bi) & 1u);
            if (lane == 0) g_keep[i2] = k;
            if (k && lane < 16) removed |= msk[i2][lane];
        }
    }
}

// ---------------- 5) ROI align -> bf16 hi/lo ----------------
__global__ void __launch_bounds__(512) roi_kernel(const float* __restrict__ feat) {
    int mrow = blockIdx.x;
    __shared__ float bxs[4];
    __shared__ int   xs0[6], xs1[6], ys0[6], ys1[6];
    __shared__ float wxs[6], wys[6];
    int tid = threadIdx.x;
    if (tid < 4) bxs[tid] = g_sel[mrow*4 + tid];
    __syncthreads();
    if (tid < 6) {
        float t = (tid + 0.5f) / 6.0f;
        float fx = (bxs[0] + t * bxs[2]) / 16.0f - 0.5f;
        float fy = (bxs[1] + t * bxs[3]) / 16.0f - 0.5f;
        fx = fminf(fmaxf(fx, 0.0f), 127.0f);
        fy = fminf(fmaxf(fy, 0.0f), 127.0f);
        int x0 = (int)floorf(fx);
        int y0 = (int)floorf(fy);
        xs0[tid] = x0; xs1[tid] = min(x0 + 1, 127); wxs[tid] = fx - (float)x0;
        ys0[tid] = y0; ys1[tid] = min(y0 + 1, 127); wys[tid] = fy - (float)y0;
    }
    __syncthreads();
    int c = tid;
    float mx[9];
    #pragma unroll
    for (int p = 0; p < 9; p++) mx[p] = -INFINITY;
    #pragma unroll
    for (int ty = 0; ty < 6; ty++) {
        int y0 = ys0[ty], y1 = ys1[ty];
        float wy = wys[ty], wy0 = 1.0f - wy;
        #pragma unroll
        for (int tx = 0; tx < 6; tx++) {
            int x0 = xs0[tx], x1 = xs1[tx];
            float wx = wxs[tx], wx0 = 1.0f - wx;
            float f00 = feat[(y0*128 + x0)*512 + c];
            float f01 = feat[(y0*128 + x1)*512 + c];
            float f10 = feat[(y1*128 + x0)*512 + c];
            float f11 = feat[(y1*128 + x1)*512 + c];
            float v = f00*wy0*wx0 + f01*wy0*wx + f10*wy*wx0 + f11*wy*wx;
            int p = (ty >> 1)*3 + (tx >> 1);
            mx[p] = fmaxf(mx[p], v);
        }
    }
    #pragma unroll
    for (int p = 0; p < 9; p++) {
        float v = mx[p];
        __nv_bfloat16 h = __float2bfloat16(v);
        __nv_bfloat16 l = __float2bfloat16(v - __bfloat162float(h));
        g_Ahi[mrow*PDIM + p*512 + c] = h;
        g_Alo[mrow*PDIM + p*512 + c] = l;
    }
}

// ---------------- 6) merged weight transpose + hi/lo split ----------------
#define W1_KT (PDIM/32)    // 144 k-tiles
#define W2_KT (HIDDEN/32)  // 32 k-tiles
__global__ void tsplit2_kernel(const float* __restrict__ W1s, const float* __restrict__ W2s) {
    __shared__ float t[32][33];
    int n0 = blockIdx.x * 32;
    int by = blockIdx.y;
    const float* W;
    __nv_bfloat16 *Th, *Tl;
    int K, k0;
    if (by < W1_KT) { W = W1s; Th = g_W1Th; Tl = g_W1Tl; K = PDIM;   k0 = by * 32; }
    else            { W = W2s; Th = g_W2Th; Tl = g_W2Tl; K = HIDDEN; k0 = (by - W1_KT) * 32; }
    int tx = threadIdx.x, ty = threadIdx.y;
    #pragma unroll
    for (int i = 0; i < 4; i++)
        t[ty + 8*i][tx] = W[(size_t)(k0 + ty + 8*i)*HIDDEN + n0 + tx];
    __syncthreads();
    #pragma unroll
    for (int i = 0; i < 4; i++) {
        float v = t[tx][ty + 8*i];
        __nv_bfloat16 h = __float2bfloat16(v);
        __nv_bfloat16 l = __float2bfloat16(v - __bfloat162float(h));
        size_t o = (size_t)(n0 + ty + 8*i)*K + k0 + tx;
        Th[o] = h;
        Tl[o] = l;
    }
}

// ---------------- 7) HMMA bf16x3 GEMM, 64x64 tiles, split-K, fused reduce ----------------
#define BM 64
#define BN 64
#define BK 32
#define SSTR 40
#define AH0 0
#define AL0 (64*SSTR)
#define BH0 (128*SSTR)
#define BL0 (192*SSTR)
#define BUFE (256*SSTR)
#define BUFB (BUFE*2)          // 20480 bytes
#define GEMM_SMEM (2*BUFB)     // 40960 bytes

__device__ __forceinline__ void gemm_load_chunk(u32 smbase, int buf,
    const __nv_bfloat16* __restrict__ Ah, const __nv_bfloat16* __restrict__ Al,
    const __nv_bfloat16* __restrict__ Bh, const __nv_bfloat16* __restrict__ Bl,
    int br, int bc, int K, int k0, int tid)
{
    u32 base = smbase + (u32)buf * BUFB;
    int row = tid >> 2;
    int cg  = (tid & 3) * 8;
    CPA16(base + (u32)(AH0 + row*SSTR + cg)*2, Ah + (size_t)(br+row)*K + k0 + cg);
    CPA16(base + (u32)(AL0 + row*SSTR + cg)*2, Al + (size_t)(br+row)*K + k0 + cg);
    CPA16(base + (u32)(BH0 + row*SSTR + cg)*2, Bh + (size_t)(bc+row)*K + k0 + cg);
    CPA16(base + (u32)(BL0 + row*SSTR + cg)*2, Bl + (size_t)(bc+row)*K + k0 + cg);
    CPA_COMMIT();
}

__global__ void __launch_bounds__(256) hgemm_kernel(
    const __nv_bfloat16* __restrict__ Ah, const __nv_bfloat16* __restrict__ Al,
    const __nv_bfloat16* __restrict__ Bh, const __nv_bfloat16* __restrict__ Bl,
    const float* __restrict__ bias,
    __nv_bfloat16* __restrict__ Chi, __nv_bfloat16* __restrict__ Clo,
    float* __restrict__ Cpart, u32* __restrict__ tick,
    int KS, int K, int ldc, int do_relu)
{
    extern __shared__ __nv_bfloat16 sm[];
    u32 smbase = smem_u32(sm);
    int tid = threadIdx.x;
    int lane = tid & 31;
    int w = tid >> 5;
    int br = blockIdx.y * BM;
    int bc = blockIdx.x * BN;
    int z  = blockIdx.z;
    int wm = (w >> 2) * 32;
    int wn = (w & 3) * 16;
    int kbase = z * KS;

    float acc[2][2][4];
    #pragma unroll
    for (int mt = 0; mt < 2; mt++)
        #pragma unroll
        for (int nt = 0; nt < 2; nt++)
            #pragma unroll
            for (int e = 0; e < 4; e++) acc[mt][nt][e] = 0.0f;

    const int NC = KS / BK;
    gemm_load_chunk(smbase, 0, Ah, Al, Bh, Bl, br, bc, K, kbase, tid);

    for (int c = 0; c < NC; c++) {
        CPA_WAIT0();
        __syncthreads();
        if (c + 1 < NC)
            gemm_load_chunk(smbase, (c+1) & 1, Ah, Al, Bh, Bl, br, bc, K,
                            kbase + (c+1)*BK, tid);

        u32 base = smbase + (u32)(c & 1) * BUFB;
        #pragma unroll
        for (int ks = 0; ks < BK; ks += 16) {
            u32 afr[2][4], afl[2][4], bfr[2][2], bfl[2][2];
            #pragma unroll
            for (int mt = 0; mt < 2; mt++) {
                u32 ra = base + (u32)(AH0 + (wm + mt*16 + (lane & 15))*SSTR
                                       + ks + (lane >> 4)*8)*2;
                ldsm4(afr[mt], ra);
                ldsm4(afl[mt], ra + (u32)(AL0 - AH0)*2);
            }
            #pragma unroll
            for (int nt = 0; nt < 2; nt++) {
                u32 rb = base + (u32)(BH0 + (wn + nt*8 + (lane & 7))*SSTR
                                       + ks + ((lane >> 3) & 1)*8)*2;
                ldsm2(bfr[nt], rb);
                ldsm2(bfl[nt], rb + (u32)(BL0 - BH0)*2);
            }
            #pragma unroll
            for (int mt = 0; mt < 2; mt++)
                #pragma unroll
                for (int nt = 0; nt < 2; nt++) {
                    mma16816(acc[mt][nt], afr[mt], bfr[nt]);
                    mma16816(acc[mt][nt], afr[mt], bfl[nt]);
                    mma16816(acc[mt][nt], afl[mt], bfr[nt]);
                }
        }
        __syncthreads();
    }

    float* myp = Cpart + (size_t)z * (MAXDET * HIDDEN);
    int g  = lane >> 2;
    int tg = lane & 3;
    #pragma unroll
    for (int mt = 0; mt < 2; mt++)
        #pragma unroll
        for (int nt = 0; nt < 2; nt++)
            #pragma unroll
            for (int e = 0; e < 4; e++) {
                int row = br + wm + mt*16 + g + (e >> 1)*8;
                int col = bc + wn + nt*8 + 2*tg + (e & 1);
                myp[(size_t)row*ldc + col] = acc[mt][nt][e];
            }
    __threadfence();
    __syncthreads();
    __shared__ int lastz;
    int tile = blockIdx.y * gridDim.x + blockIdx.x;
    if (tid == 0) lastz = (atomicAdd(&tick[tile], 1u) == (u32)(gridDim.z - 1)) ? 1 : 0;
    __syncthreads();
    if (!lastz) return;
    if (tid == 0) tick[tile] = 0;   // self-clean

    int nz = gridDim.z;
    #pragma unroll 1
    for (int i = 0; i < 16; i++) {
        int idx = tid + i*256;
        int r = idx >> 6, col = idx & 63;
        int grow = br + r, gcol = bc + col;
        float v = 0.0f;
        for (int zz = 0; zz < nz; zz++)
            v += __ldcg(&Cpart[(size_t)zz*(MAXDET*HIDDEN) + (size_t)grow*ldc + gcol]);
        v += bias[gcol];
        if (do_relu) v = fmaxf(v, 0.0f);
        __nv_bfloat16 h = __float2bfloat16(v);
        __nv_bfloat16 l = __float2bfloat16(v - __bfloat162float(h));
        Chi[(size_t)grow*ldc + gcol] = h;
        Clo[(size_t)grow*ldc + gcol] = l;
    }
}

// ---------------- 8) FC3 + unparameterize + keep gate ----------------
__global__ void fc3_final_kernel(const float* __restrict__ W3,
                                 const float* __restrict__ b3,
                                 float* __restrict__ out) {
    int mrow = blockIdx.x;
    int tid = threadIdx.x;
    float acc[4] = {0,0,0,0};
    for (int k = tid; k < HIDDEN; k += 128) {
        float hv = __bfloat162float(g_h2hi[mrow*HIDDEN + k]) +
                   __bfloat162float(g_h2lo[mrow*HIDDEN + k]);
        #pragma unroll
        for (int c = 0; c < 4; c++) acc[c] = fmaf(hv, W3[k*4 + c], acc[c]);
    }
    __shared__ float red[4][128];
    #pragma unroll
    for (int c = 0; c < 4; c++) red[c][tid] = acc[c];
    __syncthreads();
    for (int s = 64; s > 0; s >>= 1) {
        if (tid < s) {
            #pragma unroll
            for (int c = 0; c < 4; c++) red[c][tid] += red[c][tid + s];
        }
        __syncthreads();
    }
    if (tid == 0) {
        if (!g_keep[mrow]) {
            #pragma unroll
            for (int c = 0; c < 5; c++) out[mrow*5 + c] = 0.0f;
        } else {
            float d0 = red[0][0] + b3[0];
            float d1 = red[1][0] + b3[1];
            float d2 = red[2][0] + b3[2];
            float d3 = red[3][0] + b3[3];
            float sx = g_sel[mrow*4+0], sy = g_sel[mrow*4+1];
            float sw = g_sel[mrow*4+2], sh = g_sel[mrow*4+3];
            float acx = sx + sw * 0.5f;
            float acy = sy + sh * 0.5f;
            float cx = acx + d0 * sw;
            float cy = acy + d1 * sh;
            float w  = sw * expf(d2);
            float h  = sh * expf(d3);
            out[mrow*5+0] = cx - w * 0.5f;
            out[mrow*5+1] = cy - h * 0.5f;
            out[mrow*5+2] = w;
            out[mrow*5+3] = h;
            out[mrow*5+4] = g_scores[mrow];
        }
    }
}

// ---------------- launch ----------------
extern "C" void kernel_launch(void* const* d_in, const int* in_sizes, int n_in,
                              void* d_out, int out_size) {
    const float* features = (const float*)d_in[0];
    const float* rpn_obj  = (const float*)d_in[1];
    const float* rpn_reg  = (const float*)d_in[2];
    const float* W1 = (const float*)d_in[4];
    const float* b1 = (const float*)d_in[5];
    const float* W2 = (const float*)d_in[6];
    const float* b2 = (const float*)d_in[7];
    const float* W3 = (const float*)d_in[8];
    const float* b3 = (const float*)d_in[9];
    float* out = (float*)d_out;

    u64 *keys, *cand;
    u32 *hist;
    float *part;
    __nv_bfloat16 *Ahi, *Alo, *W1Th, *W1Tl, *W2Th, *W2Tl, *h1hi, *h1lo, *h2hi, *h2lo;
    cudaGetSymbolAddress((void**)&keys, g_keys);
    cudaGetSymbolAddress((void**)&cand, g_cand);
    cudaGetSymbolAddress((void**)&hist, g_hist);
    cudaGetSymbolAddress((void**)&part, g_part);
    cudaGetSymbolAddress((void**)&Ahi, g_Ahi);
    cudaGetSymbolAddress((void**)&Alo, g_Alo);
    cudaGetSymbolAddress((void**)&W1Th, g_W1Th);
    cudaGetSymbolAddress((void**)&W1Tl, g_W1Tl);
    cudaGetSymbolAddress((void**)&W2Th, g_W2Th);
    cudaGetSymbolAddress((void**)&W2Tl, g_W2Tl);
    cudaGetSymbolAddress((void**)&h1hi, g_h1hi);
    cudaGetSymbolAddress((void**)&h1lo, g_h1lo);
    cudaGetSymbolAddress((void**)&h2hi, g_h2hi);
    cudaGetSymbolAddress((void**)&h2lo, g_h2lo);

    cudaFuncSetAttribute(hgemm_kernel,
                         cudaFuncAttributeMaxDynamicSharedMemorySize, GEMM_SMEM);

    tsplit2_kernel<<<dim3(HIDDEN/32, W1_KT + W2_KT), dim3(32,8)>>>(W1, W2);

    score_kernel<<<NA/256, 256>>>(rpn_obj, keys, hist);
    compact_kernel<<<NA/256, 256>>>(keys, hist, cand);
    select_sort_kernel<<<1, 1024>>>(cand, hist, rpn_reg);
    iou_nms_kernel<<<512, 512>>>(hist);

    roi_kernel<<<512, 512>>>(features);

    dim3 gg(HIDDEN/BN, MAXDET/BM, SPLITK);   // 16 x 8 x 2 = 256 CTAs
    hgemm_kernel<<<gg, 256, GEMM_SMEM>>>(Ahi,  Alo,  W1Th, W1Tl, b1, h1hi, h1lo,
                                         part, hist + T1OFF, PDIM/SPLITK,   PDIM,   HIDDEN, 1);
    hgemm_kernel<<<gg, 256, GEMM_SMEM>>>(h1hi, h1lo, W2Th, W2Tl, b2, h2hi, h2lo,
                                         part, hist + T2OFF, HIDDEN/SPLITK, HIDDEN, HIDDEN, 1);
    fc3_final_kernel<<<MAXDET, 128>>>(W3, b3, out);
}

// round 16
// speedup vs baseline: 1.0141x; 1.0141x over previous
#include <cuda_runtime.h>
#include <cuda_bf16.h>
#include <math.h>

#define HF 128
#define WF 128
#define DF 512
#define NA 65536
#define MAXDET 512
#define HIDDEN 1024
#define PDIM (9*512)   // 4608
#define NBIN 16384
#define NCAND 1024
#define SPLITK 2

typedef unsigned long long u64;
typedef unsigned int u32;

// hist layout: [0..NBIN) bins, control words, then per-tile tickets
#define H_THR   (NBIN + 0)
#define H_TOT   (NBIN + 1)
#define H_CNT   (NBIN + 2)
#define H_DONE  (NBIN + 3)
#define H_DONE2 (NBIN + 4)
#define T1OFF   (NBIN + 16)    // 128 tickets gemm1
#define T2OFF   (NBIN + 144)   // 128 tickets gemm2
#define CTRLN   (NBIN + 512)

// ---------------- device scratch (static, zero-initialized; self-cleaning) ----------------
__device__ __align__(16) u64   g_keys[NA];
__device__ __align__(16) u32   g_hist[CTRLN];
__device__ __align__(16) u64   g_cand[NCAND];
__device__ __align__(16) float g_sel[MAXDET*4];
__device__ float g_scores[MAXDET];
__device__ int   g_valid[MAXDET];
__device__ int   g_keep[MAXDET];
__device__ __align__(16) u32   g_mask[MAXDET*16];
__device__ __align__(16) float g_part[SPLITK * MAXDET * HIDDEN];

// bf16 hi/lo split activations & weights
__device__ __align__(16) __nv_bfloat16 g_Ahi[MAXDET*PDIM];
__device__ __align__(16) __nv_bfloat16 g_Alo[MAXDET*PDIM];
__device__ __align__(16) __nv_bfloat16 g_W1Th[HIDDEN*PDIM];
__device__ __align__(16) __nv_bfloat16 g_W1Tl[HIDDEN*PDIM];
__device__ __align__(16) __nv_bfloat16 g_W2Th[HIDDEN*HIDDEN];
__device__ __align__(16) __nv_bfloat16 g_W2Tl[HIDDEN*HIDDEN];
__device__ __align__(16) __nv_bfloat16 g_h1hi[MAXDET*HIDDEN];
__device__ __align__(16) __nv_bfloat16 g_h1lo[MAXDET*HIDDEN];
__device__ __align__(16) __nv_bfloat16 g_h2hi[MAXDET*HIDDEN];
__device__ __align__(16) __nv_bfloat16 g_h2lo[MAXDET*HIDDEN];

// ---------------- low-level helpers (plain sm_103-legal PTX only) ----------------
__device__ __forceinline__ u32 smem_u32(const void* p) {
    u32 a;
    asm("{ .reg .u64 t; cvta.to.shared.u64 t, %1; cvt.u32.u64 %0, t; }" : "=r"(a) : "l"(p));
    return a;
}
#define CPA16(dst, src) \
    asm volatile("cp.async.cg.shared.global [%0], [%1], 16;" :: "r"(dst), "l"(src) : "memory")
#define CPA_COMMIT() asm volatile("cp.async.commit_group;" ::: "memory")
#define CPA_WAIT0()  asm volatile("cp.async.wait_group 0;" ::: "memory")

__device__ __forceinline__ void ldsm4(u32* r, u32 addr) {
    asm volatile("ldmatrix.sync.aligned.m8n8.x4.shared.b16 {%0,%1,%2,%3}, [%4];"
                 : "=r"(r[0]), "=r"(r[1]), "=r"(r[2]), "=r"(r[3]) : "r"(addr));
}
__device__ __forceinline__ void ldsm2(u32* r, u32 addr) {
    asm volatile("ldmatrix.sync.aligned.m8n8.x2.shared.b16 {%0,%1}, [%2];"
                 : "=r"(r[0]), "=r"(r[1]) : "r"(addr));
}
__device__ __forceinline__ void mma16816(float* d, const u32* a, const u32* b) {
    asm volatile("mma.sync.aligned.m16n8k16.row.col.f32.bf16.bf16.f32 "
                 "{%0,%1,%2,%3}, {%4,%5,%6,%7}, {%8,%9}, {%0,%1,%2,%3};"
                 : "+f"(d[0]), "+f"(d[1]), "+f"(d[2]), "+f"(d[3])
                 : "r"(a[0]), "r"(a[1]), "r"(a[2]), "r"(a[3]), "r"(b[0]), "r"(b[1]));
}

// ---------------- 1) scores + keys + histogram + fused last-block scan ----------------
__global__ void score_kernel(const float* __restrict__ obj, u64* __restrict__ keys,
                             u32* __restrict__ hist) {
    int tid = threadIdx.x;
    int n = blockIdx.x * 256 + tid;
    {
        int cell = n >> 2;
        int k = n & 3;
        float o0 = obj[cell*8 + 2*k];
        float o1 = obj[cell*8 + 2*k + 1];
        float m  = fmaxf(o0, o1);
        float e0 = expf(o0 - m);
        float e1 = expf(o1 - m);
        float s  = e1 / (e0 + e1);
        u32 bits = (s > 0.5f) ? __float_as_uint(s) : __float_as_uint(-INFINITY);
        u32 mono = (bits & 0x80000000u) ? ~bits : (bits | 0x80000000u);
        keys[n] = ((u64)mono << 32) | (u32)(~n);
        if (mono > 0xBF000000u)
            atomicAdd(&hist[(mono - 0xBF000000u) >> 9], 1u);
    }
    __threadfence();
    __syncthreads();
    __shared__ int lastBlk;
    if (tid == 0) lastBlk = (atomicAdd(&hist[H_DONE], 1u) == (u32)(gridDim.x - 1)) ? 1 : 0;
    __syncthreads();
    if (!lastBlk) return;

    u32 h[64];
    u32 seg = 0;
    uint4* hp = (uint4*)(hist + tid*64);
    #pragma unroll
    for (int v = 0; v < 16; v++) {
        uint4 x = __ldcg(&hp[v]);
        h[v*4+0] = x.x; h[v*4+1] = x.y; h[v*4+2] = x.z; h[v*4+3] = x.w;
        seg += x.x + x.y + x.z + x.w;
    }
    __shared__ u32 ps[256];
    __shared__ u32 sh_thr;
    ps[255 - tid] = seg;
    if (tid == 0) sh_thr = 0;
    __syncthreads();
    for (int off = 1; off < 256; off <<= 1) {
        u32 y = (tid >= off) ? ps[tid - off] : 0;
        __syncthreads();
        ps[tid] += y;
        __syncthreads();
    }
    u32 inc = ps[255 - tid];
    u32 exc = inc - seg;
    if (exc < 512 && inc >= 512) {
        u32 c = exc;
        #pragma unroll
        for (int k = 63; k >= 0; k--) {
            c += h[k];
            if (c >= 512) { sh_thr = (u32)(tid*64 + k); break; }
        }
    }
    uint4 z4 = make_uint4(0u, 0u, 0u, 0u);
    #pragma unroll
    for (int v = 0; v < 16; v++) hp[v] = z4;
    __syncthreads();
    if (tid == 0) {
        hist[H_THR]  = sh_thr;
        hist[H_TOT]  = ps[255];
        hist[H_DONE] = 0;
    }
}

// ---------------- 2) compact candidates ----------------
__global__ void compact_kernel(const u64* __restrict__ keys, u32* __restrict__ hist,
                               u64* __restrict__ cand) {
    int n = blockIdx.x * 256 + threadIdx.x;
    u64 key = keys[n];
    u32 hi = (u32)(key >> 32);
    bool admit;
    if (hi > 0xBF000000u) admit = ((hi - 0xBF000000u) >> 9) >= hist[H_THR];
    else                  admit = (hist[H_TOT] < 512);
    if (admit) {
        u32 p = atomicAdd(&hist[H_CNT], 1u);
        if (p < NCAND) cand[p] = key;
    }
}

// ---------------- 3) rank-sort (2 threads/candidate) + direct scatter-decode ----------------
__global__ void __launch_bounds__(1024) select_sort_kernel(const u64* __restrict__ cand,
                                                           u32* __restrict__ hist,
                                                           const float* __restrict__ reg) {
    __shared__ u64 s[NCAND];
    int tid = threadIdx.x;
    u32 cn = hist[H_CNT];
    if (cn > NCAND) cn = NCAND;
    s[tid] = (tid < (int)cn) ? cand[tid] : 0ULL;
    __syncthreads();
    if (tid == 0) {                 // self-clean after last use
        hist[H_CNT] = 0;
        hist[H_THR] = 0;
        hist[H_TOT] = 0;
    }

    int cnr = ((int)cn + 1) & ~1;       // even
    int mid = (cnr >> 1) & ~1;          // even split point
    int half = tid & 1;
    int jbeg = half ? mid : 0;
    int jend = half ? cnr : mid;

    // each candidate scanned by a thread PAIR; shfl combines partial ranks
    for (int ci = (tid >> 1); ci < NCAND; ci += 512) {   // uniform trip count
        int r = 0;
        u64 my = 0ULL;
        if (ci < (int)cn) {
            my = s[ci];
            for (int j = jbeg; j < jend; j += 2) {
                u64 a = s[j], b = s[j+1];
                r += (a > my) + (b > my);
            }
        }
        int rank = r + __shfl_xor_sync(0xffffffffu, r, 1);
        if (half == 0 && ci < (int)cn && rank < 512) {
            u32 lo = (u32)my;
            u32 hi = (u32)(my >> 32);
            u32 n  = ~lo;
            u32 fb = (hi & 0x80000000u) ? (hi ^ 0x80000000u) : ~hi;
            float sc = __uint_as_float(fb);
            int k = n & 3;
            int j = (n >> 2) & 127;
            int i = n >> 9;
            float sz = (float)((k + 1) * 32);
            int base = ((i*128 + j) * 16) + k*4;
            float r0 = reg[base+0], r1 = reg[base+1], r2 = reg[base+2], r3 = reg[base+3];
            float acx = j * 16.0f + 8.0f;
            float acy = i * 16.0f + 8.0f;
            float cx = acx + r0 * sz;
            float cy = acy + r1 * sz;
            float ww = sz * expf(r2);
            float hh = sz * expf(r3);
            int valid = (sc > 0.5f) ? 1 : 0;
            g_sel[rank*4+0] = cx - ww*0.5f;
            g_sel[rank*4+1] = cy - hh*0.5f;
            g_sel[rank*4+2] = ww;
            g_sel[rank*4+3] = hh;
            g_scores[rank] = valid ? sc : 0.0f;
            g_valid[rank]  = valid;
        }
    }
    // zero-fill unfilled tail slots when cn < 512
    if (tid >= (int)cn && tid < 512) {
        g_sel[tid*4+0] = 0.0f;
        g_sel[tid*4+1] = 0.0f;
        g_sel[tid*4+2] = 0.0f;
        g_sel[tid*4+3] = 0.0f;
        g_scores[tid] = 0.0f;
        g_valid[tid]  = 0;
    }
}

// ---------------- 4) merged: IoU ballot + ROI align + fused last-block NMS ----------------
__global__ void __launch_bounds__(512) roi_iou_nms_kernel(const float* __restrict__ feat,
                                                          u32* __restrict__ hist) {
    __shared__ float4 bx[512];
    __shared__ int   xs0[6], xs1[6], ys0[6], ys1[6];
    __shared__ float wxs[6], wys[6];
    int i = blockIdx.x;
    int j = threadIdx.x;
    bx[j] = ((const float4*)g_sel)[j];
    __syncthreads();

    // --- IoU ballot row i ---
    {
        float4 a = bx[i], b = bx[j];
        float ax2 = a.x + a.z, ay2 = a.y + a.w;
        float bx2 = b.x + b.z, by2 = b.y + b.w;
        float ix = fmaxf(0.0f, fminf(ax2, bx2) - fmaxf(a.x, b.x));
        float iy = fmaxf(0.0f, fminf(ay2, by2) - fmaxf(a.y, b.y));
        float inter = ix * iy;
        float iou = inter / (a.z*a.w + b.z*b.w - inter + 1e-8f);
        u32 ball = __ballot_sync(0xffffffffu, iou > 0.3f);
        if ((j & 31) == 0) g_mask[i*16 + (j >> 5)] = ball;
    }

    // --- ROI align for box i ---
    if (j < 6) {
        float4 bb = bx[i];
        float t = (j + 0.5f) / 6.0f;
        float fx = (bb.x + t * bb.z) / 16.0f - 0.5f;
        float fy = (bb.y + t * bb.w) / 16.0f - 0.5f;
        fx = fminf(fmaxf(fx, 0.0f), 127.0f);
        fy = fminf(fmaxf(fy, 0.0f), 127.0f);
        int x0 = (int)floorf(fx);
        int y0 = (int)floorf(fy);
        xs0[j] = x0; xs1[j] = min(x0 + 1, 127); wxs[j] = fx - (float)x0;
        ys0[j] = y0; ys1[j] = min(y0 + 1, 127); wys[j] = fy - (float)y0;
    }
    __syncthreads();
    {
        int c = j;
        float mx[9];
        #pragma unroll
        for (int p = 0; p < 9; p++) mx[p] = -INFINITY;
        #pragma unroll
        for (int ty = 0; ty < 6; ty++) {
            int y0 = ys0[ty], y1 = ys1[ty];
            float wy = wys[ty], wy0 = 1.0f - wy;
            #pragma unroll
            for (int tx = 0; tx < 6; tx++) {
                int x0 = xs0[tx], x1 = xs1[tx];
                float wx = wxs[tx], wx0 = 1.0f - wx;
                float f00 = feat[(y0*128 + x0)*512 + c];
                float f01 = feat[(y0*128 + x1)*512 + c];
                float f10 = feat[(y1*128 + x0)*512 + c];
                float f11 = feat[(y1*128 + x1)*512 + c];
                float v = f00*wy0*wx0 + f01*wy0*wx + f10*wy*wx0 + f11*wy*wx;
                int p = (ty >> 1)*3 + (tx >> 1);
                mx[p] = fmaxf(mx[p], v);
            }
        }
        #pragma unroll
        for (int p = 0; p < 9; p++) {
            float v = mx[p];
            __nv_bfloat16 h = __float2bfloat16(v);
            __nv_bfloat16 l = __float2bfloat16(v - __bfloat162float(h));
            g_Ahi[i*PDIM + p*512 + c] = h;
            g_Alo[i*PDIM + p*512 + c] = l;
        }
    }

    // --- last-block NMS scan ---
    __threadfence();
    __syncthreads();
    __shared__ int lastBlk;
    if (j == 0) lastBlk = (atomicAdd(&hist[H_DONE2], 1u) == (u32)(gridDim.x - 1)) ? 1 : 0;
    __syncthreads();
    if (!lastBlk) return;

    __shared__ u32 msk[512][16];
    __shared__ int sval[512];
    int lane = j & 31, w = j >> 5;
    #pragma unroll
    for (int r = 0; r < 16; r++) {
        int row = (j >> 4) + r*32;
        msk[row][j & 15] = __ldcg(&g_mask[row*16 + (j & 15)]);
    }
    sval[j] = g_valid[j];
    __syncthreads();
    if (j == 0) hist[H_DONE2] = 0;   // self-clean
    if (w == 0) {
        u32 removed = 0;   // lane l (<16) owns word l of the suppression set
        for (int i2 = 0; i2 < 512; i2++) {
            int wi = i2 >> 5, bi = i2 & 31;
            u32 rword = __shfl_sync(0xffffffffu, removed, wi);
            int k = sval[i2] && !((rword >> bi) & 1u);
            if (lane == 0) g_keep[i2] = k;
            if (k && lane < 16) removed |= msk[i2][lane];
        }
    }
}

// ---------------- 5) merged weight transpose + hi/lo split ----------------
#define W1_KT (PDIM/32)    // 144 k-tiles
#define W2_KT (HIDDEN/32)  // 32 k-tiles
__global__ void tsplit2_kernel(const float* __restrict__ W1s, const float* __restrict__ W2s) {
    __shared__ float t[32][33];
    int n0 = blockIdx.x * 32;
    int by = blockIdx.y;
    const float* W;
    __nv_bfloat16 *Th, *Tl;
    int K, k0;
    if (by < W1_KT) { W = W1s; Th = g_W1Th; Tl = g_W1Tl; K = PDIM;   k0 = by * 32; }
    else            { W = W2s; Th = g_W2Th; Tl = g_W2Tl; K = HIDDEN; k0 = (by - W1_KT) * 32; }
    int tx = threadIdx.x, ty = threadIdx.y;
    #pragma unroll
    for (int i = 0; i < 4; i++)
        t[ty + 8*i][tx] = W[(size_t)(k0 + ty + 8*i)*HIDDEN + n0 + tx];
    __syncthreads();
    #pragma unroll
    for (int i = 0; i < 4; i++) {
        float v = t[tx][ty + 8*i];
        __nv_bfloat16 h = __float2bfloat16(v);
        __nv_bfloat16 l = __float2bfloat16(v - __bfloat162float(h));
        size_t o = (size_t)(n0 + ty + 8*i)*K + k0 + tx;
        Th[o] = h;
        Tl[o] = l;
    }
}

// ---------------- 6) HMMA bf16x3 GEMM, 64x64 tiles, split-K, fused reduce ----------------
#define BM 64
#define BN 64
#define BK 32
#define SSTR 40
#define AH0 0
#define AL0 (64*SSTR)
#define BH0 (128*SSTR)
#define BL0 (192*SSTR)
#define BUFE (256*SSTR)
#define BUFB (BUFE*2)          // 20480 bytes
#define GEMM_SMEM (2*BUFB)     // 40960 bytes

__device__ __forceinline__ void gemm_load_chunk(u32 smbase, int buf,
    const __nv_bfloat16* __restrict__ Ah, const __nv_bfloat16* __restrict__ Al,
    const __nv_bfloat16* __restrict__ Bh, const __nv_bfloat16* __restrict__ Bl,
    int br, int bc, int K, int k0, int tid)
{
    u32 base = smbase + (u32)buf * BUFB;
    int row = tid >> 2;
    int cg  = (tid & 3) * 8;
    CPA16(base + (u32)(AH0 + row*SSTR + cg)*2, Ah + (size_t)(br+row)*K + k0 + cg);
    CPA16(base + (u32)(AL0 + row*SSTR + cg)*2, Al + (size_t)(br+row)*K + k0 + cg);
    CPA16(base + (u32)(BH0 + row*SSTR + cg)*2, Bh + (size_t)(bc+row)*K + k0 + cg);
    CPA16(base + (u32)(BL0 + row*SSTR + cg)*2, Bl + (size_t)(bc+row)*K + k0 + cg);
    CPA_COMMIT();
}

__global__ void __launch_bounds__(256) hgemm_kernel(
    const __nv_bfloat16* __restrict__ Ah, const __nv_bfloat16* __restrict__ Al,
    const __nv_bfloat16* __restrict__ Bh, const __nv_bfloat16* __restrict__ Bl,
    const float* __restrict__ bias,
    __nv_bfloat16* __restrict__ Chi, __nv_bfloat16* __restrict__ Clo,
    float* __restrict__ Cpart, u32* __restrict__ tick,
    int KS, int K, int ldc, int do_relu)
{
    extern __shared__ __nv_bfloat16 sm[];
    u32 smbase = smem_u32(sm);
    int tid = threadIdx.x;
    int lane = tid & 31;
    int w = tid >> 5;
    int br = blockIdx.y * BM;
    int bc = blockIdx.x * BN;
    int z  = blockIdx.z;
    int wm = (w >> 2) * 32;
    int wn = (w & 3) * 16;
    int kbase = z * KS;

    float acc[2][2][4];
    #pragma unroll
    for (int mt = 0; mt < 2; mt++)
        #pragma unroll
        for (int nt = 0; nt < 2; nt++)
            #pragma unroll
            for (int e = 0; e < 4; e++) acc[mt][nt][e] = 0.0f;

    const int NC = KS / BK;
    gemm_load_chunk(smbase, 0, Ah, Al, Bh, Bl, br, bc, K, kbase, tid);

    for (int c = 0; c < NC; c++) {
        CPA_WAIT0();
        __syncthreads();
        if (c + 1 < NC)
            gemm_load_chunk(smbase, (c+1) & 1, Ah, Al, Bh, Bl, br, bc, K,
                            kbase + (c+1)*BK, tid);

        u32 base = smbase + (u32)(c & 1) * BUFB;
        #pragma unroll
        for (int ks = 0; ks < BK; ks += 16) {
            u32 afr[2][4], afl[2][4], bfr[2][2], bfl[2][2];
            #pragma unroll
            for (int mt = 0; mt < 2; mt++) {
                u32 ra = base + (u32)(AH0 + (wm + mt*16 + (lane & 15))*SSTR
                                       + ks + (lane >> 4)*8)*2;
                ldsm4(afr[mt], ra);
                ldsm4(afl[mt], ra + (u32)(AL0 - AH0)*2);
            }
            #pragma unroll
            for (int nt = 0; nt < 2; nt++) {
                u32 rb = base + (u32)(BH0 + (wn + nt*8 + (lane & 7))*SSTR
                                       + ks + ((lane >> 3) & 1)*8)*2;
                ldsm2(bfr[nt], rb);
                ldsm2(bfl[nt], rb + (u32)(BL0 - BH0)*2);
            }
            #pragma unroll
            for (int mt = 0; mt < 2; mt++)
                #pragma unroll
                for (int nt = 0; nt < 2; nt++) {
                    mma16816(acc[mt][nt], afr[mt], bfr[nt]);
                    mma16816(acc[mt][nt], afr[mt], bfl[nt]);
                    mma16816(acc[mt][nt], afl[mt], bfr[nt]);
                }
        }
        __syncthreads();
    }

    float* myp = Cpart + (size_t)z * (MAXDET * HIDDEN);
    int g  = lane >> 2;
    int tg = lane & 3;
    #pragma unroll
    for (int mt = 0; mt < 2; mt++)
        #pragma unroll
        for (int nt = 0; nt < 2; nt++)
            #pragma unroll
            for (int e = 0; e < 4; e++) {
                int row = br + wm + mt*16 + g + (e >> 1)*8;
                int col = bc + wn + nt*8 + 2*tg + (e & 1);
                myp[(size_t)row*ldc + col] = acc[mt][nt][e];
            }
    __threadfence();
    __syncthreads();
    __shared__ int lastz;
    int tile = blockIdx.y * gridDim.x + blockIdx.x;
    if (tid == 0) lastz = (atomicAdd(&tick[tile], 1u) == (u32)(gridDim.z - 1)) ? 1 : 0;
    __syncthreads();
    if (!lastz) return;
    if (tid == 0) tick[tile] = 0;   // self-clean

    int nz = gridDim.z;
    #pragma unroll 1
    for (int i = 0; i < 16; i++) {
        int idx = tid + i*256;
        int r = idx >> 6, col = idx & 63;
        int grow = br + r, gcol = bc + col;
        float v = 0.0f;
        for (int zz = 0; zz < nz; zz++)
            v += __ldcg(&Cpart[(size_t)zz*(MAXDET*HIDDEN) + (size_t)grow*ldc + gcol]);
        v += bias[gcol];
        if (do_relu) v = fmaxf(v, 0.0f);
        __nv_bfloat16 h = __float2bfloat16(v);
        __nv_bfloat16 l = __float2bfloat16(v - __bfloat162float(h));
        Chi[(size_t)grow*ldc + gcol] = h;
        Clo[(size_t)grow*ldc + gcol] = l;
    }
}

// ---------------- 7) FC3 + unparameterize + keep gate ----------------
__global__ void fc3_final_kernel(const float* __restrict__ W3,
                                 const float* __restrict__ b3,
                                 float* __restrict__ out) {
    int mrow = blockIdx.x;
    int tid = threadIdx.x;
    float acc[4] = {0,0,0,0};
    for (int k = tid; k < HIDDEN; k += 128) {
        float hv = __bfloat162float(g_h2hi[mrow*HIDDEN + k]) +
                   __bfloat162float(g_h2lo[mrow*HIDDEN + k]);
        #pragma unroll
        for (int c = 0; c < 4; c++) acc[c] = fmaf(hv, W3[k*4 + c], acc[c]);
    }
    __shared__ float red[4][128];
    #pragma unroll
    for (int c = 0; c < 4; c++) red[c][tid] = acc[c];
    __syncthreads();
    for (int s = 64; s > 0; s >>= 1) {
        if (tid < s) {
            #pragma unroll
            for (int c = 0; c < 4; c++) red[c][tid] += red[c][tid + s];
        }
        __syncthreads();
    }
    if (tid == 0) {
        if (!g_keep[mrow]) {
            #pragma unroll
            for (int c = 0; c < 5; c++) out[mrow*5 + c] = 0.0f;
        } else {
            float d0 = red[0][0] + b3[0];
            float d1 = red[1][0] + b3[1];
            float d2 = red[2][0] + b3[2];
            float d3 = red[3][0] + b3[3];
            float sx = g_sel[mrow*4+0], sy = g_sel[mrow*4+1];
            float sw = g_sel[mrow*4+2], sh = g_sel[mrow*4+3];
            float acx = sx + sw * 0.5f;
            float acy = sy + sh * 0.5f;
            float cx = acx + d0 * sw;
            float cy = acy + d1 * sh;
            float w  = sw * expf(d2);
            float h  = sh * expf(d3);
            out[mrow*5+0] = cx - w * 0.5f;
            out[mrow*5+1] = cy - h * 0.5f;
            out[mrow*5+2] = w;
            out[mrow*5+3] = h;
            out[mrow*5+4] = g_scores[mrow];
        }
    }
}

// ---------------- launch ----------------
extern "C" void kernel_launch(void* const* d_in, const int* in_sizes, int n_in,
                              void* d_out, int out_size) {
    const float* features = (const float*)d_in[0];
    const float* rpn_obj  = (const float*)d_in[1];
    const float* rpn_reg  = (const float*)d_in[2];
    const float* W1 = (const float*)d_in[4];
    const float* b1 = (const float*)d_in[5];
    const float* W2 = (const float*)d_in[6];
    const float* b2 = (const float*)d_in[7];
    const float* W3 = (const float*)d_in[8];
    const float* b3 = (const float*)d_in[9];
    float* out = (float*)d_out;

    u64 *keys, *cand;
    u32 *hist;
    float *part;
    __nv_bfloat16 *Ahi, *Alo, *W1Th, *W1Tl, *W2Th, *W2Tl, *h1hi, *h1lo, *h2hi, *h2lo;
    cudaGetSymbolAddress((void**)&keys, g_keys);
    cudaGetSymbolAddress((void**)&cand, g_cand);
    cudaGetSymbolAddress((void**)&hist, g_hist);
    cudaGetSymbolAddress((void**)&part, g_part);
    cudaGetSymbolAddress((void**)&Ahi, g_Ahi);
    cudaGetSymbolAddress((void**)&Alo, g_Alo);
    cudaGetSymbolAddress((void**)&W1Th, g_W1Th);
    cudaGetSymbolAddress((void**)&W1Tl, g_W1Tl);
    cudaGetSymbolAddress((void**)&W2Th, g_W2Th);
    cudaGetSymbolAddress((void**)&W2Tl, g_W2Tl);
    cudaGetSymbolAddress((void**)&h1hi, g_h1hi);
    cudaGetSymbolAddress((void**)&h1lo, g_h1lo);
    cudaGetSymbolAddress((void**)&h2hi, g_h2hi);
    cudaGetSymbolAddress((void**)&h2lo, g_h2lo);

    cudaFuncSetAttribute(hgemm_kernel,
                         cudaFuncAttributeMaxDynamicSharedMemorySize, GEMM_SMEM);

    tsplit2_kernel<<<dim3(HIDDEN/32, W1_KT + W2_KT), dim3(32,8)>>>(W1, W2);

    score_kernel<<<NA/256, 256>>>(rpn_obj, keys, hist);
    compact_kernel<<<NA/256, 256>>>(keys, hist, cand);
    select_sort_kernel<<<1, 1024>>>(cand, hist, rpn_reg);
    roi_iou_nms_kernel<<<512, 512>>>(features, hist);

    dim3 gg(HIDDEN/BN, MAXDET/BM, SPLITK);   // 16 x 8 x 2 = 256 CTAs
    hgemm_kernel<<<gg, 256, GEMM_SMEM>>>(Ahi,  Alo,  W1Th, W1Tl, b1, h1hi, h1lo,
                                         part, hist + T1OFF, PDIM/SPLITK,   PDIM,   HIDDEN, 1);
    hgemm_kernel<<<gg, 256, GEMM_SMEM>>>(h1hi, h1lo, W2Th, W2Tl, b2, h2hi, h2lo,
                                         part, hist + T2OFF, HIDDEN/SPLITK, HIDDEN, HIDDEN, 1);
    fc3_final_kernel<<<MAXDET, 128>>>(W3, b3, out);
}